// round 2
// baseline (speedup 1.0000x reference)
#include <cuda_runtime.h>
#include <math.h>

#define NH 4
#define HD 128
#define D  512
#define TS 24
#define NB 64
#define SS 512
#define NPOS (NB*SS)   /* 32768 */
#define J   (NH*TS)    /* 96 */

// ---------------- device scratch (no allocations allowed) ----------------
__device__ __align__(16) float g_A [NB*NH*HD];      // user part of q: [b][h][e]
__device__ __align__(16) float g_Bq[TS*NH*HD];      // time part of q + bq: [t][h][e]
__device__ __align__(16) float g_K [TS*NH*HD];      // keys:   [k][h][e]
__device__ __align__(16) float g_V [TS*NH*HD];      // values: [k][h][e]
__device__ __align__(16) float g_E [NB*TS*NH*TS];   // exp(scores): [b][t][h][k]
__device__ __align__(16) float g_VU[J*D];           // V@Wu^T folded: [j=h*24+k][d]
__device__ __align__(16) float g_TL[J*TS];          // V@Wt^T folded: [j][d]

// ---------------- helpers ----------------
template<int N>
__device__ __forceinline__ float dotT(const float* __restrict__ a,
                                      const float* __restrict__ b) {
    float s0=0.f, s1=0.f, s2=0.f, s3=0.f;
    #pragma unroll
    for (int e = 0; e < N; e += 16) {
        float4 a0 = __ldg((const float4*)(a+e));
        float4 b0 = __ldg((const float4*)(b+e));
        s0 = fmaf(a0.x,b0.x, fmaf(a0.y,b0.y, fmaf(a0.z,b0.z, fmaf(a0.w,b0.w, s0))));
        float4 a1 = __ldg((const float4*)(a+e+4));
        float4 b1 = __ldg((const float4*)(b+e+4));
        s1 = fmaf(a1.x,b1.x, fmaf(a1.y,b1.y, fmaf(a1.z,b1.z, fmaf(a1.w,b1.w, s1))));
        float4 a2 = __ldg((const float4*)(a+e+8));
        float4 b2 = __ldg((const float4*)(b+e+8));
        s2 = fmaf(a2.x,b2.x, fmaf(a2.y,b2.y, fmaf(a2.z,b2.z, fmaf(a2.w,b2.w, s2))));
        float4 a3 = __ldg((const float4*)(a+e+12));
        float4 b3 = __ldg((const float4*)(b+e+12));
        s3 = fmaf(a3.x,b3.x, fmaf(a3.y,b3.y, fmaf(a3.z,b3.z, fmaf(a3.w,b3.w, s3))));
    }
    return (s0+s1)+(s2+s3);
}

// ---------------- K1: A, Bq, K, V (all K=512 dots, 69632 outputs) ----------------
__global__ void __launch_bounds__(256)
k_pre1(const float* __restrict__ ts_emb, const int* __restrict__ user_x,
       const float* __restrict__ upt,
       const float* __restrict__ Wq, const float* __restrict__ bq,
       const float* __restrict__ Wk, const float* __restrict__ bk,
       const float* __restrict__ Wv, const float* __restrict__ bv)
{
    int idx = blockIdx.x*256 + threadIdx.x;
    if (idx < 32768) {                         // g_A[b][he]
        int b = idx >> 9, he = idx & 511;
        const float* x = upt + (size_t)__ldg(user_x+b)*D;
        g_A[idx] = dotT<512>(Wq + (size_t)he*1024, x);
    } else if (idx < 45056) {                  // g_Bq[t][he]
        int i = idx - 32768; int t = i >> 9, he = i & 511;
        g_Bq[i] = dotT<512>(Wq + (size_t)he*1024 + 512, ts_emb + t*D) + __ldg(bq+he);
    } else if (idx < 57344) {                  // g_K[t][he]
        int i = idx - 45056; int t = i >> 9, he = i & 511;
        g_K[i] = dotT<512>(Wk + (size_t)he*512, ts_emb + t*D) + __ldg(bk+he);
    } else {                                   // g_V[t][he]
        int i = idx - 57344; int t = i >> 9, he = i & 511;
        g_V[i] = dotT<512>(Wv + (size_t)he*512, ts_emb + t*D) + __ldg(bv+he);
    }
}

// ---------------- K2: fold V through W_unify / W_time ----------------
__global__ void __launch_bounds__(256)
k_pre2(const float* __restrict__ Wu, const float* __restrict__ Wt)
{
    int idx = blockIdx.x*256 + threadIdx.x;   // 51456 total
    if (idx < J*D) {
        int j = idx >> 9, d = idx & 511;
        int h = j / TS, k = j - h*TS;
        g_VU[idx] = dotT<128>(&g_V[(k*NH + h)*HD], Wu + (size_t)d*D + h*HD);
    } else {
        int i = idx - J*D;                    // < 2304
        int j = i / TS, d = i - j*TS;
        int h = j / TS, k = j - h*TS;
        g_TL[i] = dotT<128>(&g_V[(k*NH + h)*HD], Wt + (size_t)d*D + h*HD);
    }
}

// ---------------- K3: E[b][t][h][k] = exp(scale * (A+Bq).K) ----------------
__global__ void __launch_bounds__(256)
k_pre3()
{
    int idx = blockIdx.x*256 + threadIdx.x;   // 147456
    int k = idx % TS;
    int h = (idx / TS) & 3;
    int t = (idx / (TS*NH)) % TS;
    int b = idx / (TS*NH*TS);
    const float* A = &g_A [(b*NH + h)*HD];
    const float* B = &g_Bq[(t*NH + h)*HD];
    const float* K = &g_K [(k*NH + h)*HD];
    float s0=0.f, s1=0.f, s2=0.f, s3=0.f;
    #pragma unroll
    for (int e = 0; e < HD; e += 16) {
        float4 a0 = *(const float4*)(A+e),   b0 = *(const float4*)(B+e),   k0 = *(const float4*)(K+e);
        s0 = fmaf(a0.x+b0.x,k0.x, fmaf(a0.y+b0.y,k0.y, fmaf(a0.z+b0.z,k0.z, fmaf(a0.w+b0.w,k0.w, s0))));
        float4 a1 = *(const float4*)(A+e+4), b1 = *(const float4*)(B+e+4), k1 = *(const float4*)(K+e+4);
        s1 = fmaf(a1.x+b1.x,k1.x, fmaf(a1.y+b1.y,k1.y, fmaf(a1.z+b1.z,k1.z, fmaf(a1.w+b1.w,k1.w, s1))));
        float4 a2 = *(const float4*)(A+e+8), b2 = *(const float4*)(B+e+8), k2 = *(const float4*)(K+e+8);
        s2 = fmaf(a2.x+b2.x,k2.x, fmaf(a2.y+b2.y,k2.y, fmaf(a2.z+b2.z,k2.z, fmaf(a2.w+b2.w,k2.w, s2))));
        float4 a3 = *(const float4*)(A+e+12),b3 = *(const float4*)(B+e+12),k3 = *(const float4*)(K+e+12);
        s3 = fmaf(a3.x+b3.x,k3.x, fmaf(a3.y+b3.y,k3.y, fmaf(a3.z+b3.z,k3.z, fmaf(a3.w+b3.w,k3.w, s3))));
    }
    float sc = ((s0+s1)+(s2+s3)) * 0.08838834764831845f;  // 1/sqrt(128)
    g_E[idx] = expf(sc);
}

// ---------------- K4: masked softmax + attn @ [VU | TL] ----------------
__global__ void __launch_bounds__(256)
k_main(const int* __restrict__ hour_x, const int* __restrict__ hour_mask,
       const float* __restrict__ b_unify, const float* __restrict__ b_time,
       float* __restrict__ out_emb, float* __restrict__ out_tl)
{
    __shared__ float s_attn[64][J+1];   // +1 pad: kills 2-way bank conflict
    __shared__ float s_tl[J][TS];

    const int tid = threadIdx.x;
    const int n0  = blockIdx.x * 64;

    for (int i = tid; i < J*TS; i += 256)
        (&s_tl[0][0])[i] = g_TL[i];

    // ---- phase 1: per-position masked softmax (4 threads/pos, one per head)
    {
        int p = tid & 63;
        int h = tid >> 6;
        int n = n0 + p;
        int b = n >> 9;
        int t = __ldg(hour_x + n);
        const int4*   mrow = (const int4*)(hour_mask + (size_t)n*TS);
        const float4* erow = (const float4*)(&g_E[((b*TS + t)*NH + h)*TS]);
        float wv[TS];
        float sum = 0.f;
        #pragma unroll
        for (int q = 0; q < 6; q++) {
            int4   m = __ldg(mrow + q);
            float4 e = erow[q];
            wv[4*q+0] = (m.x == 1) ? 0.f : e.x;
            wv[4*q+1] = (m.y == 1) ? 0.f : e.y;
            wv[4*q+2] = (m.z == 1) ? 0.f : e.z;
            wv[4*q+3] = (m.w == 1) ? 0.f : e.w;
            sum += (wv[4*q+0]+wv[4*q+1]) + (wv[4*q+2]+wv[4*q+3]);
        }
        float inv = 1.f / sum;
        #pragma unroll
        for (int k = 0; k < TS; k++) s_attn[p][h*TS + k] = wv[k] * inv;
    }
    __syncthreads();

    // ---- phase 2: 64x512 = attn[64x96] @ VU[96x512], reg-tiled 4x8
    const int tx = tid & 15;
    const int ty = tid >> 4;
    const int p0 = ty * 4;

    for (int c = 0; c < 4; c++) {
        const int d0 = c*128 + tx*8;
        float4 acc[4][2];
        #pragma unroll
        for (int i = 0; i < 4; i++) {
            acc[i][0] = make_float4(0.f,0.f,0.f,0.f);
            acc[i][1] = make_float4(0.f,0.f,0.f,0.f);
        }
        const float* vp = g_VU + d0;
        #pragma unroll 8
        for (int k = 0; k < J; k++) {
            float4 v0 = __ldg((const float4*)(vp + k*D));
            float4 v1 = __ldg((const float4*)(vp + k*D + 4));
            #pragma unroll
            for (int i = 0; i < 4; i++) {
                float a = s_attn[p0+i][k];
                acc[i][0].x = fmaf(a, v0.x, acc[i][0].x);
                acc[i][0].y = fmaf(a, v0.y, acc[i][0].y);
                acc[i][0].z = fmaf(a, v0.z, acc[i][0].z);
                acc[i][0].w = fmaf(a, v0.w, acc[i][0].w);
                acc[i][1].x = fmaf(a, v1.x, acc[i][1].x);
                acc[i][1].y = fmaf(a, v1.y, acc[i][1].y);
                acc[i][1].z = fmaf(a, v1.z, acc[i][1].z);
                acc[i][1].w = fmaf(a, v1.w, acc[i][1].w);
            }
        }
        float4 bu0 = __ldg((const float4*)(b_unify + d0));
        float4 bu1 = __ldg((const float4*)(b_unify + d0 + 4));
        #pragma unroll
        for (int i = 0; i < 4; i++) {
            float4 r0 = acc[i][0]; r0.x+=bu0.x; r0.y+=bu0.y; r0.z+=bu0.z; r0.w+=bu0.w;
            float4 r1 = acc[i][1]; r1.x+=bu1.x; r1.y+=bu1.y; r1.z+=bu1.z; r1.w+=bu1.w;
            float* orow = out_emb + (size_t)(n0+p0+i)*D + d0;
            *(float4*)(orow)     = r0;
            *(float4*)(orow + 4) = r1;
        }
    }

    // ---- phase 3: time logits = attn @ TL[96x24]
    #pragma unroll
    for (int r = 0; r < 6; r++) {
        int o = tid + 256*r;          // 0..1535 over 64 pos x 24 dims
        int p = o / TS;
        int d = o - p*TS;
        float acc = 0.f;
        #pragma unroll 8
        for (int j = 0; j < J; j++)
            acc = fmaf(s_attn[p][j], s_tl[j][d], acc);
        out_tl[(size_t)(n0+p)*TS + d] = acc + __ldg(b_time + d);
    }
}

// ---------------- launch ----------------
extern "C" void kernel_launch(void* const* d_in, const int* in_sizes, int n_in,
                              void* d_out, int out_size)
{
    const float* ts_emb    = (const float*)d_in[0];
    // d_in[1] smoothed_timeslot_embedded: unused by reference
    // d_in[2] user_embedded: unused by reference
    const int*   user_x    = (const int*)  d_in[3];
    const int*   hour_x    = (const int*)  d_in[4];
    const int*   hour_mask = (const int*)  d_in[5];
    const float* upt       = (const float*)d_in[6];
    const float* Wq        = (const float*)d_in[7];
    const float* bq        = (const float*)d_in[8];
    const float* Wk        = (const float*)d_in[9];
    const float* bk        = (const float*)d_in[10];
    const float* Wv        = (const float*)d_in[11];
    const float* bv        = (const float*)d_in[12];
    const float* Wu        = (const float*)d_in[13];
    const float* bu        = (const float*)d_in[14];
    const float* Wt        = (const float*)d_in[15];
    const float* bt        = (const float*)d_in[16];

    float* out_emb = (float*)d_out;
    float* out_tl  = out_emb + (size_t)NPOS * D;

    k_pre1<<<272, 256>>>(ts_emb, user_x, upt, Wq, bq, Wk, bk, Wv, bv);
    k_pre2<<<201, 256>>>(Wu, Wt);
    k_pre3<<<576, 256>>>();
    k_main<<<512, 256>>>(hour_x, hour_mask, bu, bt, out_emb, out_tl);
}

// round 4
// speedup vs baseline: 1.6929x; 1.6929x over previous
#include <cuda_runtime.h>
#include <cuda_bf16.h>
#include <math.h>
#include <stdint.h>

#define NH 4
#define HD 128
#define D  512
#define TS 24
#define NB 64
#define NPOS 32768
#define J   96
#define JP  104      /* padded j stride (bf16 / f32 elements) */

// ---------------- device scratch ----------------
__device__ __align__(16)  float g_A [NB*NH*HD];
__device__ __align__(16)  float g_Bq[TS*NH*HD];
__device__ __align__(16)  float g_K [TS*NH*HD];
__device__ __align__(16)  float g_V [TS*NH*HD];
__device__ __align__(16)  float g_E [NB*TS*NH*TS];
__device__ __align__(128) __nv_bfloat16 g_Bh[D*JP];   // VU^T hi: [d][j] padded
__device__ __align__(128) __nv_bfloat16 g_Bl[D*JP];   // VU^T lo
__device__ __align__(16)  float g_TL[J*TS];

// ---------------- ptx helpers (baseline sm_90 features only) ----------------
__device__ __forceinline__ uint32_t smem_u32(const void* p){
    uint32_t a;
    asm("{ .reg .u64 t; cvta.to.shared.u64 t, %1; cvt.u32.u64 %0, t; }" : "=r"(a) : "l"(p));
    return a;
}
__device__ __forceinline__ void bulk_g2s(uint32_t dst, const void* src,
                                         uint32_t bytes, uint32_t mbar){
    asm volatile(
        "cp.async.bulk.shared::cluster.global.mbarrier::complete_tx::bytes [%0], [%1], %2, [%3];"
        :: "r"(dst), "l"(src), "r"(bytes), "r"(mbar) : "memory");
}
#define MBAR_INIT(a, c)  asm volatile("mbarrier.init.shared.b64 [%0], %1;" :: "r"(a), "r"(c) : "memory")
#define MBAR_EXPECT(a,b) asm volatile("mbarrier.arrive.expect_tx.shared.b64 _, [%0], %1;" :: "r"(a), "r"(b) : "memory")
#define MBAR_WAIT(a, ph) do { \
    uint32_t _m=(a), _p=(ph), _d; \
    asm volatile("{\n\t.reg .pred p;\n\t" \
        "mbarrier.try_wait.parity.acquire.cta.shared::cta.b64 p, [%1], %2;\n\t" \
        "selp.b32 %0, 1, 0, p;\n\t}" : "=r"(_d) : "r"(_m), "r"(_p) : "memory"); \
    if (!_d) { asm volatile("{\n\t.reg .pred P1;\n\t" \
        "W_%=:\n\tmbarrier.try_wait.parity.acquire.cta.shared::cta.b64 P1, [%0], %1, 0x989680;\n\t" \
        "@P1 bra.uni WD_%=;\n\tbra.uni W_%=;\n\tWD_%=:\n\t}" :: "r"(_m), "r"(_p) : "memory"); } \
} while(0)

#define MMA16816(c, a, b) \
    asm volatile("mma.sync.aligned.m16n8k16.row.col.f32.bf16.bf16.f32 " \
        "{%0,%1,%2,%3}, {%4,%5,%6,%7}, {%8,%9}, {%0,%1,%2,%3};" \
        : "+f"((c)[0]), "+f"((c)[1]), "+f"((c)[2]), "+f"((c)[3]) \
        : "r"((a)[0]), "r"((a)[1]), "r"((a)[2]), "r"((a)[3]), \
          "r"((b)[0]), "r"((b)[1]))

// ---------------- fp32 dot helper ----------------
template<int N>
__device__ __forceinline__ float dotT(const float* __restrict__ a,
                                      const float* __restrict__ b) {
    float s0=0.f, s1=0.f, s2=0.f, s3=0.f;
    #pragma unroll
    for (int e = 0; e < N; e += 16) {
        float4 a0 = __ldg((const float4*)(a+e));
        float4 b0 = __ldg((const float4*)(b+e));
        s0 = fmaf(a0.x,b0.x, fmaf(a0.y,b0.y, fmaf(a0.z,b0.z, fmaf(a0.w,b0.w, s0))));
        float4 a1 = __ldg((const float4*)(a+e+4));
        float4 b1 = __ldg((const float4*)(b+e+4));
        s1 = fmaf(a1.x,b1.x, fmaf(a1.y,b1.y, fmaf(a1.z,b1.z, fmaf(a1.w,b1.w, s1))));
        float4 a2 = __ldg((const float4*)(a+e+8));
        float4 b2 = __ldg((const float4*)(b+e+8));
        s2 = fmaf(a2.x,b2.x, fmaf(a2.y,b2.y, fmaf(a2.z,b2.z, fmaf(a2.w,b2.w, s2))));
        float4 a3 = __ldg((const float4*)(a+e+12));
        float4 b3 = __ldg((const float4*)(b+e+12));
        s3 = fmaf(a3.x,b3.x, fmaf(a3.y,b3.y, fmaf(a3.z,b3.z, fmaf(a3.w,b3.w, s3))));
    }
    return (s0+s1)+(s2+s3);
}

// ---------------- K1: A, Bq, K, V — 8 outputs/thread, shared W row ----------------
__global__ void __launch_bounds__(256)
k_pre1(const float* __restrict__ ts_emb, const int* __restrict__ user_x,
       const float* __restrict__ upt,
       const float* __restrict__ Wq, const float* __restrict__ bq,
       const float* __restrict__ Wk, const float* __restrict__ bk,
       const float* __restrict__ Wv, const float* __restrict__ bv)
{
    int idx = blockIdx.x*256 + threadIdx.x;
    if (idx >= 8704) return;

    const float* w;
    const float* x[8];
    float bias = 0.f;
    int he, grp, sec;
    if (idx < 4096) {                       // g_A: 512 he x 8 user-groups
        sec = 0; he = idx & 511; grp = idx >> 9;
        w = Wq + (size_t)he*1024;
        #pragma unroll
        for (int i = 0; i < 8; i++)
            x[i] = upt + (size_t)__ldg(user_x + grp*8 + i)*D;
    } else if (idx < 5632) {                // g_Bq
        sec = 1; int i0 = idx - 4096; he = i0 & 511; grp = i0 >> 9;
        w = Wq + (size_t)he*1024 + 512; bias = __ldg(bq + he);
        #pragma unroll
        for (int i = 0; i < 8; i++) x[i] = ts_emb + (grp*8 + i)*D;
    } else if (idx < 7168) {                // g_K
        sec = 2; int i0 = idx - 5632; he = i0 & 511; grp = i0 >> 9;
        w = Wk + (size_t)he*512; bias = __ldg(bk + he);
        #pragma unroll
        for (int i = 0; i < 8; i++) x[i] = ts_emb + (grp*8 + i)*D;
    } else {                                // g_V
        sec = 3; int i0 = idx - 7168; he = i0 & 511; grp = i0 >> 9;
        w = Wv + (size_t)he*512; bias = __ldg(bv + he);
        #pragma unroll
        for (int i = 0; i < 8; i++) x[i] = ts_emb + (grp*8 + i)*D;
    }

    float acc[8] = {0,0,0,0,0,0,0,0};
    for (int e = 0; e < D; e += 4) {
        float4 wv = __ldg((const float4*)(w + e));
        #pragma unroll
        for (int i = 0; i < 8; i++) {
            float4 xv = __ldg((const float4*)(x[i] + e));
            acc[i] = fmaf(wv.x,xv.x, fmaf(wv.y,xv.y, fmaf(wv.z,xv.z, fmaf(wv.w,xv.w, acc[i]))));
        }
    }
    float* dst = (sec==0) ? g_A : (sec==1) ? g_Bq : (sec==2) ? g_K : g_V;
    #pragma unroll
    for (int i = 0; i < 8; i++)
        dst[(size_t)(grp*8 + i)*D + he] = acc[i] + bias;
}

// ---------------- K2: fold V through W_unify -> bf16 hi/lo [d][JP]; W_time -> g_TL ----------------
__global__ void __launch_bounds__(256)
k_pre2(const float* __restrict__ Wu, const float* __restrict__ Wt)
{
    int idx = blockIdx.x*256 + threadIdx.x;
    if (idx < J*D) {                          // j-outer: V row broadcast per warp
        int j = idx >> 9, d = idx & 511;
        int h = j / TS, k = j - h*TS;
        float val = dotT<128>(&g_V[(k*NH + h)*HD], Wu + (size_t)d*D + h*HD);
        __nv_bfloat16 hi = __float2bfloat16(val);
        __nv_bfloat16 lo = __float2bfloat16(val - __bfloat162float(hi));
        g_Bh[(size_t)d*JP + j] = hi;
        g_Bl[(size_t)d*JP + j] = lo;
    } else if (idx < J*D + J*TS) {
        int i = idx - J*D;
        int j = i / TS, d = i - j*TS;
        int h = j / TS, k = j - h*TS;
        g_TL[j*TS + d] = dotT<128>(&g_V[(k*NH + h)*HD], Wt + (size_t)d*D + h*HD);
    }
}

// ---------------- K3: E = exp(scale * (A+Bq).K) — 12 k per thread ----------------
__global__ void __launch_bounds__(128)
k_pre3()
{
    int idx = blockIdx.x*128 + threadIdx.x;   // 12288 = 64b*24t*4h*2kh
    if (idx >= 12288) return;
    int kh = idx & 1;
    int h  = (idx >> 1) & 3;
    int t  = (idx >> 3) % TS;
    int b  = idx / (TS*8);
    const float* A  = g_A  + (b*NH + h)*HD;
    const float* Bq = g_Bq + (t*NH + h)*HD;

    float acc[12] = {0,0,0,0,0,0,0,0,0,0,0,0};
    for (int e0 = 0; e0 < HD; e0 += 32) {
        float4 q[8];
        #pragma unroll
        for (int i = 0; i < 8; i++) {
            float4 a = *(const float4*)(A + e0 + i*4);
            float4 bb = *(const float4*)(Bq + e0 + i*4);
            q[i] = make_float4(a.x+bb.x, a.y+bb.y, a.z+bb.z, a.w+bb.w);
        }
        #pragma unroll
        for (int k = 0; k < 12; k++) {
            const float* K = g_K + ((kh*12 + k)*NH + h)*HD + e0;
            float s = 0.f;
            #pragma unroll
            for (int i = 0; i < 8; i++) {
                float4 kv = *(const float4*)(K + i*4);
                s = fmaf(q[i].x,kv.x, fmaf(q[i].y,kv.y, fmaf(q[i].z,kv.z, fmaf(q[i].w,kv.w, s))));
            }
            acc[k] += s;
        }
    }
    float* E = g_E + ((size_t)(b*TS + t)*NH + h)*TS + kh*12;
    #pragma unroll
    for (int k = 0; k < 12; k++)
        E[k] = expf(acc[k] * 0.08838834764831845f);
}

// ---------------- K4: softmax + HMMA GEMM + TL ----------------
#define SM_MBAR  0
#define SM_BIAS  64                       /* 512 f32 */
#define SM_TLB   2112                     /* 96*24 f32 */
#define SM_ATTN  11392                    /* 128*104 f32 = 53248 */
#define SM_AHI   64640                    /* 128*104 bf16 = 26624 */
#define SM_ALO   91264
#define SM_B     117888                   /* 2 stages x 53248 (hi+lo) */
#define SM_STAGE 53248
#define SM_TOTAL 224384

__global__ void __launch_bounds__(256, 1)
k_main(const int* __restrict__ hour_x, const int* __restrict__ hour_mask,
       const float* __restrict__ b_unify, const float* __restrict__ b_time,
       float* __restrict__ out_emb, float* __restrict__ out_tl)
{
    extern __shared__ char sm[];
    const uint32_t sb = smem_u32(sm);
    const int tid  = threadIdx.x;
    const int wid  = tid >> 5;
    const int lane = tid & 31;
    const int n0   = blockIdx.x * 128;

    if (tid == 0) { MBAR_INIT(sb + SM_MBAR, 1); MBAR_INIT(sb + SM_MBAR + 8, 1); }
    for (int i = tid; i < 512; i += 256)  ((float*)(sm + SM_BIAS))[i] = __ldg(b_unify + i);
    for (int i = tid; i < J*TS; i += 256) ((float*)(sm + SM_TLB))[i]  = g_TL[i];
    __syncthreads();

    if (tid == 0) {        // prologue: stage chunks 0,1 (hi+lo contiguous per chunk row range)
        #pragma unroll
        for (int c = 0; c < 2; c++) {
            uint32_t mb = sb + SM_MBAR + 8*c;
            MBAR_EXPECT(mb, SM_STAGE);
            bulk_g2s(sb + SM_B + c*SM_STAGE,          g_Bh + (size_t)c*128*JP, 128*JP*2, mb);
            bulk_g2s(sb + SM_B + c*SM_STAGE + 26624,  g_Bl + (size_t)c*128*JP, 128*JP*2, mb);
        }
    }

    // ---- softmax -> s_attn[p][JP] fp32 ----
    float* s_attn = (float*)(sm + SM_ATTN);
    #pragma unroll
    for (int r = 0; r < 2; r++) {
        int task = tid + 256*r;          // 512 = 128p x 4h
        int p = task & 127, h = task >> 7;
        int n = n0 + p;
        int b = n >> 9;
        int t = __ldg(hour_x + n);
        const float4* erow = (const float4*)(g_E + ((size_t)(b*TS + t)*NH + h)*TS);
        const int4*   mrow = (const int4*)(hour_mask + (size_t)n*TS);
        float wv[TS]; float sum = 0.f;
        #pragma unroll
        for (int q = 0; q < 6; q++) {
            int4   m = __ldg(mrow + q);
            float4 e = erow[q];
            wv[4*q+0] = (m.x == 1) ? 0.f : e.x;
            wv[4*q+1] = (m.y == 1) ? 0.f : e.y;
            wv[4*q+2] = (m.z == 1) ? 0.f : e.z;
            wv[4*q+3] = (m.w == 1) ? 0.f : e.w;
            sum += (wv[4*q+0]+wv[4*q+1]) + (wv[4*q+2]+wv[4*q+3]);
        }
        float inv = 1.f / sum;
        #pragma unroll
        for (int k = 0; k < TS; k++) s_attn[p*JP + h*TS + k] = wv[k] * inv;
    }
    __syncthreads();

    // ---- convert A to bf16 hi/lo ----
    uint32_t* sAhU = (uint32_t*)(sm + SM_AHI);
    uint32_t* sAlU = (uint32_t*)(sm + SM_ALO);
    for (int i = tid; i < 128*48; i += 256) {
        int p = i / 48, jp = i - p*48;
        float a0 = s_attn[p*JP + jp*2];
        float a1 = s_attn[p*JP + jp*2 + 1];
        __nv_bfloat16 h0 = __float2bfloat16(a0);
        __nv_bfloat16 h1 = __float2bfloat16(a1);
        __nv_bfloat16 l0 = __float2bfloat16(a0 - __bfloat162float(h0));
        __nv_bfloat16 l1 = __float2bfloat16(a1 - __bfloat162float(h1));
        sAhU[p*(JP/2) + jp] = (uint32_t)__bfloat16_as_ushort(h1) << 16 | __bfloat16_as_ushort(h0);
        sAlU[p*(JP/2) + jp] = (uint32_t)__bfloat16_as_ushort(l1) << 16 | __bfloat16_as_ushort(l0);
    }
    __syncthreads();

    // ---- HMMA mainloop: 4 N-chunks of 128, warp tile 64x32 ----
    const int grp = lane >> 2, qid = lane & 3;
    const int wm  = wid & 1,   wn  = wid >> 1;
    const int ar  = wm*64 + grp;
    const float* bias = (const float*)(sm + SM_BIAS);

    for (int c = 0; c < 4; c++) {
        MBAR_WAIT(sb + SM_MBAR + 8*(c & 1), (c >> 1) & 1);
        const uint32_t* bhU = (const uint32_t*)(sm + SM_B + (c & 1)*SM_STAGE);
        const uint32_t* blU = bhU + 26624/4;

        float acc[4][4][4];
        #pragma unroll
        for (int mt = 0; mt < 4; mt++)
            #pragma unroll
            for (int nt = 0; nt < 4; nt++)
                #pragma unroll
                for (int i = 0; i < 4; i++) acc[mt][nt][i] = 0.f;

        #pragma unroll
        for (int ks = 0; ks < 6; ks++) {
            const int ca = ks*8 + qid;
            uint32_t ah[4][4], al[4][4];
            #pragma unroll
            for (int mt = 0; mt < 4; mt++) {
                int r0 = (ar + mt*16)*(JP/2) + ca;
                int r1 = r0 + 8*(JP/2);
                ah[mt][0] = sAhU[r0];   ah[mt][1] = sAhU[r1];
                ah[mt][2] = sAhU[r0+4]; ah[mt][3] = sAhU[r1+4];
                al[mt][0] = sAlU[r0];   al[mt][1] = sAlU[r1];
                al[mt][2] = sAlU[r0+4]; al[mt][3] = sAlU[r1+4];
            }
            uint32_t bh[4][2], bl[4][2];
            #pragma unroll
            for (int nt = 0; nt < 4; nt++) {
                int nb = (wn*32 + nt*8 + grp)*(JP/2) + ca;
                bh[nt][0] = bhU[nb]; bh[nt][1] = bhU[nb+4];
                bl[nt][0] = blU[nb]; bl[nt][1] = blU[nb+4];
            }
            #pragma unroll
            for (int mt = 0; mt < 4; mt++)
                #pragma unroll
                for (int nt = 0; nt < 4; nt++) {
                    MMA16816(acc[mt][nt], ah[mt], bh[nt]);
                    MMA16816(acc[mt][nt], ah[mt], bl[nt]);
                    MMA16816(acc[mt][nt], al[mt], bh[nt]);
                }
        }

        // store with bias
        #pragma unroll
        for (int nt = 0; nt < 4; nt++) {
            int d = c*128 + wn*32 + nt*8 + qid*2;
            float bx = bias[d], by = bias[d+1];
            #pragma unroll
            for (int mt = 0; mt < 4; mt++) {
                int row = n0 + wm*64 + mt*16 + grp;
                float2 o0 = make_float2(acc[mt][nt][0] + bx, acc[mt][nt][1] + by);
                float2 o1 = make_float2(acc[mt][nt][2] + bx, acc[mt][nt][3] + by);
                *(float2*)(out_emb + (size_t)row*D + d)     = o0;
                *(float2*)(out_emb + (size_t)(row+8)*D + d) = o1;
            }
        }
        __syncthreads();
        if (tid == 0 && c + 2 < 4) {
            int nc = c + 2;
            uint32_t mb = sb + SM_MBAR + 8*(nc & 1);
            MBAR_EXPECT(mb, SM_STAGE);
            bulk_g2s(sb + SM_B + (nc & 1)*SM_STAGE,         g_Bh + (size_t)nc*128*JP, 128*JP*2, mb);
            bulk_g2s(sb + SM_B + (nc & 1)*SM_STAGE + 26624, g_Bl + (size_t)nc*128*JP, 128*JP*2, mb);
        }
    }

    // ---- time logits: attn[128x96] @ TL[96x24] ----
    {
        int p  = tid >> 1;
        int d0 = (tid & 1)*12;
        const float* arow = s_attn + p*JP;
        const float* stl  = (const float*)(sm + SM_TLB);
        float acc[12];
        #pragma unroll
        for (int i = 0; i < 12; i++) acc[i] = 0.f;
        #pragma unroll 4
        for (int j = 0; j < J; j++) {
            float a = arow[j];
            float4 t0 = *(const float4*)(stl + j*TS + d0);
            float4 t1 = *(const float4*)(stl + j*TS + d0 + 4);
            float4 t2 = *(const float4*)(stl + j*TS + d0 + 8);
            acc[0]=fmaf(a,t0.x,acc[0]); acc[1]=fmaf(a,t0.y,acc[1]); acc[2]=fmaf(a,t0.z,acc[2]); acc[3]=fmaf(a,t0.w,acc[3]);
            acc[4]=fmaf(a,t1.x,acc[4]); acc[5]=fmaf(a,t1.y,acc[5]); acc[6]=fmaf(a,t1.z,acc[6]); acc[7]=fmaf(a,t1.w,acc[7]);
            acc[8]=fmaf(a,t2.x,acc[8]); acc[9]=fmaf(a,t2.y,acc[9]); acc[10]=fmaf(a,t2.z,acc[10]); acc[11]=fmaf(a,t2.w,acc[11]);
        }
        float* orow = out_tl + (size_t)(n0 + p)*TS + d0;
        #pragma unroll
        for (int i = 0; i < 12; i++)
            orow[i] = acc[i] + __ldg(b_time + d0 + i);
    }
}

// ---------------- launch ----------------
extern "C" void kernel_launch(void* const* d_in, const int* in_sizes, int n_in,
                              void* d_out, int out_size)
{
    const float* ts_emb    = (const float*)d_in[0];
    const int*   user_x    = (const int*)  d_in[3];
    const int*   hour_x    = (const int*)  d_in[4];
    const int*   hour_mask = (const int*)  d_in[5];
    const float* upt       = (const float*)d_in[6];
    const float* Wq        = (const float*)d_in[7];
    const float* bq        = (const float*)d_in[8];
    const float* Wk        = (const float*)d_in[9];
    const float* bk        = (const float*)d_in[10];
    const float* Wv        = (const float*)d_in[11];
    const float* bv        = (const float*)d_in[12];
    const float* Wu        = (const float*)d_in[13];
    const float* bu        = (const float*)d_in[14];
    const float* Wt        = (const float*)d_in[15];
    const float* bt        = (const float*)d_in[16];

    float* out_emb = (float*)d_out;
    float* out_tl  = out_emb + (size_t)NPOS * D;

    cudaFuncSetAttribute(k_main, cudaFuncAttributeMaxDynamicSharedMemorySize, SM_TOTAL);

    k_pre1<<<34, 256>>>(ts_emb, user_x, upt, Wq, bq, Wk, bk, Wv, bv);
    k_pre2<<<201, 256>>>(Wu, Wt);
    k_pre3<<<96, 128>>>();
    k_main<<<256, 256, SM_TOTAL>>>(hour_x, hour_mask, bu, bt, out_emb, out_tl);
}

// round 5
// speedup vs baseline: 3.3332x; 1.9689x over previous
#include <cuda_runtime.h>
#include <cuda_bf16.h>
#include <math.h>
#include <stdint.h>

#define NH 4
#define HD 128
#define D  512
#define TS 24
#define NB 64
#define NPOS 32768
#define J   96
#define JP  104      /* padded j stride */

// ---------------- device scratch ----------------
__device__ __align__(16)  float g_A [NB*NH*HD];
__device__ __align__(16)  float g_Bq[TS*NH*HD];
__device__ __align__(16)  float g_K [TS*NH*HD];
__device__ __align__(16)  float g_V [TS*NH*HD];
__device__ __align__(16)  float g_E [NB*TS*NH*TS];
__device__ __align__(128) __nv_bfloat16 g_Bh[D*JP];   // VU^T hi: [d][j]
__device__ __align__(128) __nv_bfloat16 g_Bl[D*JP];   // VU^T lo
__device__ __align__(16)  float g_TL[J*TS];

// ---------------- helpers ----------------
__device__ __forceinline__ uint32_t smem_u32(const void* p){
    uint32_t a;
    asm("{ .reg .u64 t; cvta.to.shared.u64 t, %1; cvt.u32.u64 %0, t; }" : "=r"(a) : "l"(p));
    return a;
}
__device__ __forceinline__ void bulk_g2s(uint32_t dst, const void* src,
                                         uint32_t bytes, uint32_t mbar){
    asm volatile(
        "cp.async.bulk.shared::cluster.global.mbarrier::complete_tx::bytes [%0], [%1], %2, [%3];"
        :: "r"(dst), "l"(src), "r"(bytes), "r"(mbar) : "memory");
}
#define MBAR_INIT(a, c)  asm volatile("mbarrier.init.shared.b64 [%0], %1;" :: "r"(a), "r"(c) : "memory")
#define MBAR_EXPECT(a,b) asm volatile("mbarrier.arrive.expect_tx.shared.b64 _, [%0], %1;" :: "r"(a), "r"(b) : "memory")
#define MBAR_WAIT(a, ph) do { \
    uint32_t _m=(a), _p=(ph), _d; \
    asm volatile("{\n\t.reg .pred p;\n\t" \
        "mbarrier.try_wait.parity.acquire.cta.shared::cta.b64 p, [%1], %2;\n\t" \
        "selp.b32 %0, 1, 0, p;\n\t}" : "=r"(_d) : "r"(_m), "r"(_p) : "memory"); \
    if (!_d) { asm volatile("{\n\t.reg .pred P1;\n\t" \
        "W_%=:\n\tmbarrier.try_wait.parity.acquire.cta.shared::cta.b64 P1, [%0], %1, 0x989680;\n\t" \
        "@P1 bra.uni WD_%=;\n\tbra.uni W_%=;\n\tWD_%=:\n\t}" :: "r"(_m), "r"(_p) : "memory"); } \
} while(0)

#define MMA16816(c, a, b) \
    asm volatile("mma.sync.aligned.m16n8k16.row.col.f32.bf16.bf16.f32 " \
        "{%0,%1,%2,%3}, {%4,%5,%6,%7}, {%8,%9}, {%0,%1,%2,%3};" \
        : "+f"((c)[0]), "+f"((c)[1]), "+f"((c)[2]), "+f"((c)[3]) \
        : "r"((a)[0]), "r"((a)[1]), "r"((a)[2]), "r"((a)[3]), \
          "r"((b)[0]), "r"((b)[1]))

__device__ __forceinline__ float wredsum(float v){
    #pragma unroll
    for (int o = 16; o; o >>= 1) v += __shfl_xor_sync(0xFFFFFFFFu, v, o);
    return v;
}
__device__ __forceinline__ float dot4(float4 a, float4 b){
    return fmaf(a.x,b.x, fmaf(a.y,b.y, fmaf(a.z,b.z, a.w*b.w)));
}

// ---------------- K1: A, Bq, K, V ----------------
// warp = (he, row-group of 8); block = 8 warps (8 he) sharing x rows (L1-hot).
// rowgroup 0..7 = A user-groups; 8..10 Bq; 11..13 K; 14..16 V.  grid = 17*64 = 1088
__global__ void __launch_bounds__(256)
k_pre1(const float* __restrict__ ts_emb, const int* __restrict__ user_x,
       const float* __restrict__ upt,
       const float* __restrict__ Wq, const float* __restrict__ bq,
       const float* __restrict__ Wk, const float* __restrict__ bk,
       const float* __restrict__ Wv, const float* __restrict__ bv)
{
    const int wid  = threadIdx.x >> 5;
    const int lane = threadIdx.x & 31;
    const int rg   = blockIdx.x >> 6;          // 0..16
    const int he   = (blockIdx.x & 63)*8 + wid;

    const float* w;
    const float* x[8];
    float bias = 0.f;
    float* dst;
    int row0;
    if (rg < 8) {
        w = Wq + (size_t)he*1024; dst = g_A; row0 = rg*8;
        #pragma unroll
        for (int i = 0; i < 8; i++)
            x[i] = upt + (size_t)__ldg(user_x + rg*8 + i)*D;
    } else if (rg < 11) {
        int g = rg - 8;
        w = Wq + (size_t)he*1024 + 512; bias = __ldg(bq + he);
        dst = g_Bq; row0 = g*8;
        #pragma unroll
        for (int i = 0; i < 8; i++) x[i] = ts_emb + (g*8 + i)*D;
    } else if (rg < 14) {
        int g = rg - 11;
        w = Wk + (size_t)he*512; bias = __ldg(bk + he);
        dst = g_K; row0 = g*8;
        #pragma unroll
        for (int i = 0; i < 8; i++) x[i] = ts_emb + (g*8 + i)*D;
    } else {
        int g = rg - 14;
        w = Wv + (size_t)he*512; bias = __ldg(bv + he);
        dst = g_V; row0 = g*8;
        #pragma unroll
        for (int i = 0; i < 8; i++) x[i] = ts_emb + (g*8 + i)*D;
    }

    float acc[8] = {0,0,0,0,0,0,0,0};
    #pragma unroll
    for (int ch = 0; ch < 4; ch++) {
        int e = ch*128 + lane*4;
        float4 w4 = __ldg((const float4*)(w + e));
        #pragma unroll
        for (int i = 0; i < 8; i++) {
            float4 x4 = __ldg((const float4*)(x[i] + e));
            acc[i] = fmaf(w4.x,x4.x, fmaf(w4.y,x4.y, fmaf(w4.z,x4.z, fmaf(w4.w,x4.w, acc[i]))));
        }
    }
    float r = 0.f;
    #pragma unroll
    for (int i = 0; i < 8; i++) {
        float s = wredsum(acc[i]);
        if (lane == i) r = s;
    }
    if (lane < 8)
        dst[(size_t)(row0 + lane)*D + he] = r + bias;
}

// ---------------- K2: VU = V@Wu^T -> bf16 hi/lo [d][JP]; TL = V@Wt^T ----------------
// warp-task: (j, d-group of 8). VU tasks 96*64 = 6144; TL tasks 96*3 = 288. grid 804
__global__ void __launch_bounds__(256)
k_pre2(const float* __restrict__ Wu, const float* __restrict__ Wt)
{
    const int wid  = threadIdx.x >> 5;
    const int lane = threadIdx.x & 31;
    int task = blockIdx.x*8 + wid;
    if (task < 6144) {
        int j  = task >> 6;             // block's 8 warps share j -> V row L1-hot
        int dg = task & 63;
        int h = j / TS, k = j - h*TS;
        float4 vr = *(const float4*)(g_V + (k*NH + h)*HD + lane*4);
        const float* wbase = Wu + h*HD + lane*4;
        float val = 0.f;
        #pragma unroll
        for (int dd = 0; dd < 8; dd++) {
            int d = dg*8 + dd;
            float4 w4 = __ldg((const float4*)(wbase + (size_t)d*D));
            float s = wredsum(dot4(vr, w4));
            if (lane == dd) val = s;
        }
        if (lane < 8) {
            int d = dg*8 + lane;
            __nv_bfloat16 hi = __float2bfloat16(val);
            __nv_bfloat16 lo = __float2bfloat16(val - __bfloat162float(hi));
            g_Bh[(size_t)d*JP + j] = hi;
            g_Bl[(size_t)d*JP + j] = lo;
        }
    } else if (task < 6144 + 288) {
        int t2 = task - 6144;
        int j  = t2 / 3;
        int dg = t2 - j*3;
        int h = j / TS, k = j - h*TS;
        float4 vr = *(const float4*)(g_V + (k*NH + h)*HD + lane*4);
        const float* wbase = Wt + h*HD + lane*4;
        float val = 0.f;
        #pragma unroll
        for (int dd = 0; dd < 8; dd++) {
            int d = dg*8 + dd;
            float4 w4 = __ldg((const float4*)(wbase + (size_t)d*D));
            float s = wredsum(dot4(vr, w4));
            if (lane == dd) val = s;
        }
        if (lane < 8)
            g_TL[j*TS + dg*8 + lane] = val;
    }
}

// ---------------- K3: E = exp(scale*(A+Bq).K) ----------------
// block = (b, h, tgroup of 8); warp = one t; lanes split e; grid 64*4*3 = 768
__global__ void __launch_bounds__(256)
k_pre3()
{
    const int wid  = threadIdx.x >> 5;
    const int lane = threadIdx.x & 31;
    int blk = blockIdx.x;
    int b   = blk / 12;
    int rem = blk - b*12;
    int h   = rem >> 2;          // 0..2? no: 12 = 4h*3tg -> h = rem/3
    h = rem / 3;
    int tg  = rem - h*3;
    int t   = tg*8 + wid;

    float4 qa = *(const float4*)(g_A  + (b*NH + h)*HD + lane*4);
    float4 qb = *(const float4*)(g_Bq + (t*NH + h)*HD + lane*4);
    float4 q = make_float4(qa.x+qb.x, qa.y+qb.y, qa.z+qb.z, qa.w+qb.w);

    float val = 0.f;
    #pragma unroll
    for (int k = 0; k < TS; k++) {
        float4 kv = *(const float4*)(g_K + (k*NH + h)*HD + lane*4);
        float s = wredsum(dot4(q, kv));
        if (lane == k) val = s;
    }
    if (lane < TS)
        g_E[((size_t)(b*TS + t)*NH + h)*TS + lane] = expf(val * 0.08838834764831845f);
}

// ---------------- K4: softmax + HMMA GEMM + TL (512 threads) ----------------
#define SM_MBAR  0
#define SM_BIAS  64
#define SM_TLB   2112
#define SM_ATTN  11392                    /* 128*104 f32 */
#define SM_AHI   64640                    /* 128*52 u32 */
#define SM_ALO   91264
#define SM_B     117888                   /* 2 stages x 53248 */
#define SM_STAGE 53248
#define SM_TOTAL 224384

__global__ void __launch_bounds__(512, 1)
k_main(const int* __restrict__ hour_x, const int* __restrict__ hour_mask,
       const float* __restrict__ b_unify, const float* __restrict__ b_time,
       float* __restrict__ out_emb, float* __restrict__ out_tl)
{
    extern __shared__ char sm[];
    const uint32_t sb = smem_u32(sm);
    const int tid  = threadIdx.x;
    const int wid  = tid >> 5;
    const int lane = tid & 31;
    const int n0   = blockIdx.x * 128;

    if (tid == 0) { MBAR_INIT(sb + SM_MBAR, 1); MBAR_INIT(sb + SM_MBAR + 8, 1); }
    if (tid < 512) ((float*)(sm + SM_BIAS))[tid] = __ldg(b_unify + tid);
    for (int i = tid; i < J*TS; i += 512) ((float*)(sm + SM_TLB))[i] = g_TL[i];
    __syncthreads();

    if (tid == 0) {
        #pragma unroll
        for (int c = 0; c < 2; c++) {
            uint32_t mb = sb + SM_MBAR + 8*c;
            MBAR_EXPECT(mb, SM_STAGE);
            bulk_g2s(sb + SM_B + c*SM_STAGE,          g_Bh + (size_t)c*128*JP, 128*JP*2, mb);
            bulk_g2s(sb + SM_B + c*SM_STAGE + 26624,  g_Bl + (size_t)c*128*JP, 128*JP*2, mb);
        }
    }

    // ---- softmax: one (p,h) per thread ----
    float* s_attn = (float*)(sm + SM_ATTN);
    {
        int p = tid & 127, h = tid >> 7;
        int n = n0 + p;
        int b = n >> 9;
        int t = __ldg(hour_x + n);
        const float4* erow = (const float4*)(g_E + ((size_t)(b*TS + t)*NH + h)*TS);
        const int4*   mrow = (const int4*)(hour_mask + (size_t)n*TS);
        float wv[TS]; float sum = 0.f;
        #pragma unroll
        for (int q = 0; q < 6; q++) {
            int4   m = __ldg(mrow + q);
            float4 e = erow[q];
            wv[4*q+0] = (m.x == 1) ? 0.f : e.x;
            wv[4*q+1] = (m.y == 1) ? 0.f : e.y;
            wv[4*q+2] = (m.z == 1) ? 0.f : e.z;
            wv[4*q+3] = (m.w == 1) ? 0.f : e.w;
            sum += (wv[4*q+0]+wv[4*q+1]) + (wv[4*q+2]+wv[4*q+3]);
        }
        float inv = 1.f / sum;
        #pragma unroll
        for (int k = 0; k < TS; k++) s_attn[p*JP + h*TS + k] = wv[k] * inv;
    }
    __syncthreads();

    // ---- A hi/lo bf16 ----
    uint32_t* sAhU = (uint32_t*)(sm + SM_AHI);
    uint32_t* sAlU = (uint32_t*)(sm + SM_ALO);
    for (int i = tid; i < 128*48; i += 512) {
        int p = i / 48, jp = i - p*48;
        float a0 = s_attn[p*JP + jp*2];
        float a1 = s_attn[p*JP + jp*2 + 1];
        __nv_bfloat16 h0 = __float2bfloat16(a0);
        __nv_bfloat16 h1 = __float2bfloat16(a1);
        __nv_bfloat16 l0 = __float2bfloat16(a0 - __bfloat162float(h0));
        __nv_bfloat16 l1 = __float2bfloat16(a1 - __bfloat162float(h1));
        sAhU[p*(JP/2) + jp] = (uint32_t)__bfloat16_as_ushort(h1) << 16 | __bfloat16_as_ushort(h0);
        sAlU[p*(JP/2) + jp] = (uint32_t)__bfloat16_as_ushort(l1) << 16 | __bfloat16_as_ushort(l0);
    }
    __syncthreads();

    // ---- HMMA mainloop: 16 warps, warp tile 32x32 ----
    const int grp = lane >> 2, qid = lane & 3;
    const int wm  = wid & 3,   wn  = wid >> 2;
    const float* bias = (const float*)(sm + SM_BIAS);

    for (int c = 0; c < 4; c++) {
        MBAR_WAIT(sb + SM_MBAR + 8*(c & 1), (c >> 1) & 1);
        const uint32_t* bhU = (const uint32_t*)(sm + SM_B + (c & 1)*SM_STAGE);
        const uint32_t* blU = bhU + 26624/4;

        float acc[2][4][4];
        #pragma unroll
        for (int mt = 0; mt < 2; mt++)
            #pragma unroll
            for (int nt = 0; nt < 4; nt++)
                #pragma unroll
                for (int i = 0; i < 4; i++) acc[mt][nt][i] = 0.f;

        #pragma unroll
        for (int ks = 0; ks < 6; ks++) {
            const int ca = ks*8 + qid;
            uint32_t ah[2][4], al[2][4];
            #pragma unroll
            for (int mt = 0; mt < 2; mt++) {
                int r0 = (wm*32 + mt*16 + grp)*(JP/2) + ca;
                int r1 = r0 + 8*(JP/2);
                ah[mt][0] = sAhU[r0];   ah[mt][1] = sAhU[r1];
                ah[mt][2] = sAhU[r0+4]; ah[mt][3] = sAhU[r1+4];
                al[mt][0] = sAlU[r0];   al[mt][1] = sAlU[r1];
                al[mt][2] = sAlU[r0+4]; al[mt][3] = sAlU[r1+4];
            }
            uint32_t bh[4][2], bl[4][2];
            #pragma unroll
            for (int nt = 0; nt < 4; nt++) {
                int nb = (wn*32 + nt*8 + grp)*(JP/2) + ca;
                bh[nt][0] = bhU[nb]; bh[nt][1] = bhU[nb+4];
                bl[nt][0] = blU[nb]; bl[nt][1] = blU[nb+4];
            }
            #pragma unroll
            for (int mt = 0; mt < 2; mt++)
                #pragma unroll
                for (int nt = 0; nt < 4; nt++) {
                    MMA16816(acc[mt][nt], ah[mt], bh[nt]);
                    MMA16816(acc[mt][nt], ah[mt], bl[nt]);
                    MMA16816(acc[mt][nt], al[mt], bh[nt]);
                }
        }

        #pragma unroll
        for (int nt = 0; nt < 4; nt++) {
            int d = c*128 + wn*32 + nt*8 + qid*2;
            float bx = bias[d], by = bias[d+1];
            #pragma unroll
            for (int mt = 0; mt < 2; mt++) {
                int row = n0 + wm*32 + mt*16 + grp;
                float2 o0 = make_float2(acc[mt][nt][0] + bx, acc[mt][nt][1] + by);
                float2 o1 = make_float2(acc[mt][nt][2] + bx, acc[mt][nt][3] + by);
                *(float2*)(out_emb + (size_t)row*D + d)     = o0;
                *(float2*)(out_emb + (size_t)(row+8)*D + d) = o1;
            }
        }
        __syncthreads();
        if (tid == 0 && c + 2 < 4) {
            int nc = c + 2;
            uint32_t mb = sb + SM_MBAR + 8*(nc & 1);
            MBAR_EXPECT(mb, SM_STAGE);
            bulk_g2s(sb + SM_B + (nc & 1)*SM_STAGE,         g_Bh + (size_t)nc*128*JP, 128*JP*2, mb);
            bulk_g2s(sb + SM_B + (nc & 1)*SM_STAGE + 26624, g_Bl + (size_t)nc*128*JP, 128*JP*2, mb);
        }
    }

    // ---- time logits: attn[128x96] @ TL[96x24] ----
    {
        int p  = tid >> 2;
        int d0 = (tid & 3)*6;
        const float* arow = s_attn + p*JP;
        const float* stl  = (const float*)(sm + SM_TLB);
        float acc6[6] = {0,0,0,0,0,0};
        #pragma unroll 4
        for (int j = 0; j < J; j++) {
            float a = arow[j];
            const float* tr = stl + j*TS + d0;
            #pragma unroll
            for (int i = 0; i < 6; i++) acc6[i] = fmaf(a, tr[i], acc6[i]);
        }
        float* orow = out_tl + (size_t)(n0 + p)*TS + d0;
        #pragma unroll
        for (int i = 0; i < 6; i++)
            orow[i] = acc6[i] + __ldg(b_time + d0 + i);
    }
}

// ---------------- launch ----------------
extern "C" void kernel_launch(void* const* d_in, const int* in_sizes, int n_in,
                              void* d_out, int out_size)
{
    const float* ts_emb    = (const float*)d_in[0];
    const int*   user_x    = (const int*)  d_in[3];
    const int*   hour_x    = (const int*)  d_in[4];
    const int*   hour_mask = (const int*)  d_in[5];
    const float* upt       = (const float*)d_in[6];
    const float* Wq        = (const float*)d_in[7];
    const float* bq        = (const float*)d_in[8];
    const float* Wk        = (const float*)d_in[9];
    const float* bk        = (const float*)d_in[10];
    const float* Wv        = (const float*)d_in[11];
    const float* bv        = (const float*)d_in[12];
    const float* Wu        = (const float*)d_in[13];
    const float* bu        = (const float*)d_in[14];
    const float* Wt        = (const float*)d_in[15];
    const float* bt        = (const float*)d_in[16];

    float* out_emb = (float*)d_out;
    float* out_tl  = out_emb + (size_t)NPOS * D;

    cudaFuncSetAttribute(k_main, cudaFuncAttributeMaxDynamicSharedMemorySize, SM_TOTAL);

    k_pre1<<<1088, 256>>>(ts_emb, user_x, upt, Wq, bq, Wk, bk, Wv, bv);
    k_pre2<<<804, 256>>>(Wu, Wt);
    k_pre3<<<768, 256>>>();
    k_main<<<256, 512, SM_TOTAL>>>(hour_x, hour_mask, bu, bt, out_emb, out_tl);
}

// round 6
// speedup vs baseline: 3.5114x; 1.0535x over previous
#include <cuda_runtime.h>
#include <cuda_bf16.h>
#include <math.h>
#include <stdint.h>

#define NH 4
#define HD 128
#define D  512
#define TS 24
#define NB 64
#define NPOS 32768
#define J   96
#define JP  104      /* padded j stride */

// ---------------- device scratch ----------------
__device__ __align__(16)  float g_A [NB*NH*HD];
__device__ __align__(16)  float g_Bq[TS*NH*HD];
__device__ __align__(16)  float g_K [TS*NH*HD];
__device__ __align__(16)  float g_V [TS*NH*HD];
__device__ __align__(16)  float g_E [NB*TS*NH*TS];
__device__ __align__(128) __nv_bfloat16 g_Bh[D*JP];   // VU^T hi: [d][j]
__device__ __align__(128) __nv_bfloat16 g_Bl[D*JP];   // VU^T lo
__device__ __align__(16)  float g_TL[J*TS];

// ---------------- helpers ----------------
__device__ __forceinline__ uint32_t smem_u32(const void* p){
    uint32_t a;
    asm("{ .reg .u64 t; cvta.to.shared.u64 t, %1; cvt.u32.u64 %0, t; }" : "=r"(a) : "l"(p));
    return a;
}
__device__ __forceinline__ void bulk_g2s(uint32_t dst, const void* src,
                                         uint32_t bytes, uint32_t mbar){
    asm volatile(
        "cp.async.bulk.shared::cluster.global.mbarrier::complete_tx::bytes [%0], [%1], %2, [%3];"
        :: "r"(dst), "l"(src), "r"(bytes), "r"(mbar) : "memory");
}
#define MBAR_INIT(a, c)  asm volatile("mbarrier.init.shared.b64 [%0], %1;" :: "r"(a), "r"(c) : "memory")
#define MBAR_EXPECT(a,b) asm volatile("mbarrier.arrive.expect_tx.shared.b64 _, [%0], %1;" :: "r"(a), "r"(b) : "memory")
#define MBAR_WAIT(a, ph) do { \
    uint32_t _m=(a), _p=(ph), _d; \
    asm volatile("{\n\t.reg .pred p;\n\t" \
        "mbarrier.try_wait.parity.acquire.cta.shared::cta.b64 p, [%1], %2;\n\t" \
        "selp.b32 %0, 1, 0, p;\n\t}" : "=r"(_d) : "r"(_m), "r"(_p) : "memory"); \
    if (!_d) { asm volatile("{\n\t.reg .pred P1;\n\t" \
        "W_%=:\n\tmbarrier.try_wait.parity.acquire.cta.shared::cta.b64 P1, [%0], %1, 0x989680;\n\t" \
        "@P1 bra.uni WD_%=;\n\tbra.uni W_%=;\n\tWD_%=:\n\t}" :: "r"(_m), "r"(_p) : "memory"); } \
} while(0)

#define MMA16816(c, a, b0v, b1v) \
    asm volatile("mma.sync.aligned.m16n8k16.row.col.f32.bf16.bf16.f32 " \
        "{%0,%1,%2,%3}, {%4,%5,%6,%7}, {%8,%9}, {%0,%1,%2,%3};" \
        : "+f"((c)[0]), "+f"((c)[1]), "+f"((c)[2]), "+f"((c)[3]) \
        : "r"((a)[0]), "r"((a)[1]), "r"((a)[2]), "r"((a)[3]), \
          "r"(b0v), "r"(b1v))

#define LDMX4(r, addr) \
    asm volatile("ldmatrix.sync.aligned.m8n8.x4.shared.b16 {%0,%1,%2,%3}, [%4];" \
        : "=r"((r)[0]), "=r"((r)[1]), "=r"((r)[2]), "=r"((r)[3]) : "r"(addr))

__device__ __forceinline__ float wredsum(float v){
    #pragma unroll
    for (int o = 16; o; o >>= 1) v += __shfl_xor_sync(0xFFFFFFFFu, v, o);
    return v;
}
__device__ __forceinline__ float dot4(float4 a, float4 b){
    return fmaf(a.x,b.x, fmaf(a.y,b.y, fmaf(a.z,b.z, a.w*b.w)));
}

// ---------------- K1: A, Bq, K, V ----------------
__global__ void __launch_bounds__(256)
k_pre1(const float* __restrict__ ts_emb, const int* __restrict__ user_x,
       const float* __restrict__ upt,
       const float* __restrict__ Wq, const float* __restrict__ bq,
       const float* __restrict__ Wk, const float* __restrict__ bk,
       const float* __restrict__ Wv, const float* __restrict__ bv)
{
    const int wid  = threadIdx.x >> 5;
    const int lane = threadIdx.x & 31;
    const int rg   = blockIdx.x >> 6;
    const int he   = (blockIdx.x & 63)*8 + wid;

    const float* w;
    const float* x[8];
    float bias = 0.f;
    float* dst;
    int row0;
    if (rg < 8) {
        w = Wq + (size_t)he*1024; dst = g_A; row0 = rg*8;
        #pragma unroll
        for (int i = 0; i < 8; i++)
            x[i] = upt + (size_t)__ldg(user_x + rg*8 + i)*D;
    } else if (rg < 11) {
        int g = rg - 8;
        w = Wq + (size_t)he*1024 + 512; bias = __ldg(bq + he);
        dst = g_Bq; row0 = g*8;
        #pragma unroll
        for (int i = 0; i < 8; i++) x[i] = ts_emb + (g*8 + i)*D;
    } else if (rg < 14) {
        int g = rg - 11;
        w = Wk + (size_t)he*512; bias = __ldg(bk + he);
        dst = g_K; row0 = g*8;
        #pragma unroll
        for (int i = 0; i < 8; i++) x[i] = ts_emb + (g*8 + i)*D;
    } else {
        int g = rg - 14;
        w = Wv + (size_t)he*512; bias = __ldg(bv + he);
        dst = g_V; row0 = g*8;
        #pragma unroll
        for (int i = 0; i < 8; i++) x[i] = ts_emb + (g*8 + i)*D;
    }

    float acc[8] = {0,0,0,0,0,0,0,0};
    #pragma unroll
    for (int ch = 0; ch < 4; ch++) {
        int e = ch*128 + lane*4;
        float4 w4 = __ldg((const float4*)(w + e));
        #pragma unroll
        for (int i = 0; i < 8; i++) {
            float4 x4 = __ldg((const float4*)(x[i] + e));
            acc[i] = fmaf(w4.x,x4.x, fmaf(w4.y,x4.y, fmaf(w4.z,x4.z, fmaf(w4.w,x4.w, acc[i]))));
        }
    }
    float r = 0.f;
    #pragma unroll
    for (int i = 0; i < 8; i++) {
        float s = wredsum(acc[i]);
        if (lane == i) r = s;
    }
    if (lane < 8)
        dst[(size_t)(row0 + lane)*D + he] = r + bias;
}

// ---------------- K2: VU -> bf16 hi/lo [d][JP]; TL ----------------
__global__ void __launch_bounds__(256)
k_pre2(const float* __restrict__ Wu, const float* __restrict__ Wt)
{
    const int wid  = threadIdx.x >> 5;
    const int lane = threadIdx.x & 31;
    int task = blockIdx.x*8 + wid;
    if (task < 6144) {
        int j  = task >> 6;
        int dg = task & 63;
        int h = j / TS, k = j - h*TS;
        float4 vr = *(const float4*)(g_V + (k*NH + h)*HD + lane*4);
        const float* wbase = Wu + h*HD + lane*4;
        float val = 0.f;
        #pragma unroll
        for (int dd = 0; dd < 8; dd++) {
            int d = dg*8 + dd;
            float4 w4 = __ldg((const float4*)(wbase + (size_t)d*D));
            float s = wredsum(dot4(vr, w4));
            if (lane == dd) val = s;
        }
        if (lane < 8) {
            int d = dg*8 + lane;
            __nv_bfloat16 hi = __float2bfloat16(val);
            __nv_bfloat16 lo = __float2bfloat16(val - __bfloat162float(hi));
            g_Bh[(size_t)d*JP + j] = hi;
            g_Bl[(size_t)d*JP + j] = lo;
        }
    } else if (task < 6144 + 288) {
        int t2 = task - 6144;
        int j  = t2 / 3;
        int dg = t2 - j*3;
        int h = j / TS, k = j - h*TS;
        float4 vr = *(const float4*)(g_V + (k*NH + h)*HD + lane*4);
        const float* wbase = Wt + h*HD + lane*4;
        float val = 0.f;
        #pragma unroll
        for (int dd = 0; dd < 8; dd++) {
            int d = dg*8 + dd;
            float4 w4 = __ldg((const float4*)(wbase + (size_t)d*D));
            float s = wredsum(dot4(vr, w4));
            if (lane == dd) val = s;
        }
        if (lane < 8)
            g_TL[j*TS + dg*8 + lane] = val;
    }
}

// ---------------- K3: E = exp(scale*(A+Bq).K) ----------------
__global__ void __launch_bounds__(256)
k_pre3()
{
    const int wid  = threadIdx.x >> 5;
    const int lane = threadIdx.x & 31;
    int blk = blockIdx.x;
    int b   = blk / 12;
    int rem = blk - b*12;
    int h   = rem / 3;
    int tg  = rem - h*3;
    int t   = tg*8 + wid;

    float4 qa = *(const float4*)(g_A  + (b*NH + h)*HD + lane*4);
    float4 qb = *(const float4*)(g_Bq + (t*NH + h)*HD + lane*4);
    float4 q = make_float4(qa.x+qb.x, qa.y+qb.y, qa.z+qb.z, qa.w+qb.w);

    float val = 0.f;
    #pragma unroll
    for (int k = 0; k < TS; k++) {
        float4 kv = *(const float4*)(g_K + (k*NH + h)*HD + lane*4);
        float s = wredsum(dot4(q, kv));
        if (lane == k) val = s;
    }
    if (lane < TS)
        g_E[((size_t)(b*TS + t)*NH + h)*TS + lane] = expf(val * 0.08838834764831845f);
}

// ---------------- K4: softmax + HMMA(ldmatrix) GEMM + TL ----------------
#define SM_MBAR  0
#define SM_BIAS  64
#define SM_TLB   2112
#define SM_ATTN  11392                    /* 128*104 f32 */
#define SM_AHI   64640                    /* 128 rows x 208B */
#define SM_ALO   91264
#define SM_B     117888                   /* 2 stages x 53248 (hi 26624 + lo 26624) */
#define SM_STAGE 53248
#define SM_TOTAL 224384
#define LO_OFF   26624                    /* ALO-AHI and Bl-Bh offsets */

__global__ void __launch_bounds__(512, 1)
k_main(const int* __restrict__ hour_x, const int* __restrict__ hour_mask,
       const float* __restrict__ b_unify, const float* __restrict__ b_time,
       float* __restrict__ out_emb, float* __restrict__ out_tl)
{
    extern __shared__ char sm[];
    const uint32_t sb = smem_u32(sm);
    const int tid  = threadIdx.x;
    const int wid  = tid >> 5;
    const int lane = tid & 31;
    const int n0   = blockIdx.x * 128;

    if (tid == 0) { MBAR_INIT(sb + SM_MBAR, 1); MBAR_INIT(sb + SM_MBAR + 8, 1); }
    if (tid < 512) ((float*)(sm + SM_BIAS))[tid] = __ldg(b_unify + tid);
    for (int i = tid; i < J*TS; i += 512) ((float*)(sm + SM_TLB))[i] = g_TL[i];
    __syncthreads();

    if (tid == 0) {
        #pragma unroll
        for (int c = 0; c < 2; c++) {
            uint32_t mb = sb + SM_MBAR + 8*c;
            MBAR_EXPECT(mb, SM_STAGE);
            bulk_g2s(sb + SM_B + c*SM_STAGE,          g_Bh + (size_t)c*128*JP, 128*JP*2, mb);
            bulk_g2s(sb + SM_B + c*SM_STAGE + LO_OFF, g_Bl + (size_t)c*128*JP, 128*JP*2, mb);
        }
    }

    // ---- softmax: one (p,h) per thread ----
    float* s_attn = (float*)(sm + SM_ATTN);
    {
        int p = tid & 127, h = tid >> 7;
        int n = n0 + p;
        int b = n >> 9;
        int t = __ldg(hour_x + n);
        const float4* erow = (const float4*)(g_E + ((size_t)(b*TS + t)*NH + h)*TS);
        const int4*   mrow = (const int4*)(hour_mask + (size_t)n*TS);
        float wv[TS]; float sum = 0.f;
        #pragma unroll
        for (int q = 0; q < 6; q++) {
            int4   m = __ldg(mrow + q);
            float4 e = erow[q];
            wv[4*q+0] = (m.x == 1) ? 0.f : e.x;
            wv[4*q+1] = (m.y == 1) ? 0.f : e.y;
            wv[4*q+2] = (m.z == 1) ? 0.f : e.z;
            wv[4*q+3] = (m.w == 1) ? 0.f : e.w;
            sum += (wv[4*q+0]+wv[4*q+1]) + (wv[4*q+2]+wv[4*q+3]);
        }
        float inv = 1.f / sum;
        #pragma unroll
        for (int k = 0; k < TS; k++) s_attn[p*JP + h*TS + k] = wv[k] * inv;
    }
    __syncthreads();

    // ---- A hi/lo bf16 ----
    uint32_t* sAhU = (uint32_t*)(sm + SM_AHI);
    uint32_t* sAlU = (uint32_t*)(sm + SM_ALO);
    for (int i = tid; i < 128*48; i += 512) {
        int p = i / 48, jp = i - p*48;
        float a0 = s_attn[p*JP + jp*2];
        float a1 = s_attn[p*JP + jp*2 + 1];
        __nv_bfloat16 h0 = __float2bfloat16(a0);
        __nv_bfloat16 h1 = __float2bfloat16(a1);
        __nv_bfloat16 l0 = __float2bfloat16(a0 - __bfloat162float(h0));
        __nv_bfloat16 l1 = __float2bfloat16(a1 - __bfloat162float(h1));
        sAhU[p*(JP/2) + jp] = (uint32_t)__bfloat16_as_ushort(h1) << 16 | __bfloat16_as_ushort(h0);
        sAlU[p*(JP/2) + jp] = (uint32_t)__bfloat16_as_ushort(l1) << 16 | __bfloat16_as_ushort(l0);
    }
    __syncthreads();

    // ---- HMMA mainloop: 16 warps, warp tile 32x32, ldmatrix fragment loads ----
    const int wm = wid & 3, wn = wid >> 2;
    const int grp = lane >> 2, qid = lane & 3;
    const float* bias = (const float*)(sm + SM_BIAS);

    // A ldmatrix lane address: matrices [ (r0-7,k0-7), (r8-15,k0-7), (r0-7,k8-15), (r8-15,k8-15) ]
    const int am = lane >> 3, r8 = lane & 7;
    const uint32_t aBase = sb + SM_AHI
        + (uint32_t)(wm*32 + (am & 1)*8 + r8)*208u + (uint32_t)((am >> 1) & 1)*16u;
    // B ldmatrix lane address: matrices [ b0_ntA, b1_ntA, b0_ntB, b1_ntB ]
    const uint32_t bRow = (uint32_t)(wn*32 + ((am >> 1) & 1)*8 + r8)*208u + (uint32_t)(am & 1)*16u;

    for (int c = 0; c < 4; c++) {
        MBAR_WAIT(sb + SM_MBAR + 8*(c & 1), (c >> 1) & 1);
        const uint32_t bBase = sb + SM_B + (uint32_t)(c & 1)*SM_STAGE + bRow;

        float acc[2][4][4];
        #pragma unroll
        for (int mt = 0; mt < 2; mt++)
            #pragma unroll
            for (int nt = 0; nt < 4; nt++)
                #pragma unroll
                for (int i = 0; i < 4; i++) acc[mt][nt][i] = 0.f;

        #pragma unroll
        for (int ks = 0; ks < 6; ks++) {
            const uint32_t ak = aBase + ks*32;
            const uint32_t bk = bBase + ks*32;
            uint32_t ah[2][4], al[2][4], bh[2][4], bl[2][4];
            LDMX4(ah[0], ak);
            LDMX4(ah[1], ak + 16*208);
            LDMX4(al[0], ak + LO_OFF);
            LDMX4(al[1], ak + LO_OFF + 16*208);
            LDMX4(bh[0], bk);
            LDMX4(bh[1], bk + 16*208);
            LDMX4(bl[0], bk + LO_OFF);
            LDMX4(bl[1], bk + LO_OFF + 16*208);
            #pragma unroll
            for (int mt = 0; mt < 2; mt++)
                #pragma unroll
                for (int nt = 0; nt < 4; nt++) {
                    const int pr = nt >> 1, sub = (nt & 1)*2;
                    MMA16816(acc[mt][nt], ah[mt], bh[pr][sub], bh[pr][sub+1]);
                    MMA16816(acc[mt][nt], ah[mt], bl[pr][sub], bl[pr][sub+1]);
                    MMA16816(acc[mt][nt], al[mt], bh[pr][sub], bh[pr][sub+1]);
                }
        }

        #pragma unroll
        for (int nt = 0; nt < 4; nt++) {
            int d = c*128 + wn*32 + nt*8 + qid*2;
            float bx = bias[d], by = bias[d+1];
            #pragma unroll
            for (int mt = 0; mt < 2; mt++) {
                int row = n0 + wm*32 + mt*16 + grp;
                float2 o0 = make_float2(acc[mt][nt][0] + bx, acc[mt][nt][1] + by);
                float2 o1 = make_float2(acc[mt][nt][2] + bx, acc[mt][nt][3] + by);
                *(float2*)(out_emb + (size_t)row*D + d)     = o0;
                *(float2*)(out_emb + (size_t)(row+8)*D + d) = o1;
            }
        }
        __syncthreads();
        if (tid == 0 && c + 2 < 4) {
            int nc = c + 2;
            uint32_t mb = sb + SM_MBAR + 8*(nc & 1);
            MBAR_EXPECT(mb, SM_STAGE);
            bulk_g2s(sb + SM_B + (nc & 1)*SM_STAGE,          g_Bh + (size_t)nc*128*JP, 128*JP*2, mb);
            bulk_g2s(sb + SM_B + (nc & 1)*SM_STAGE + LO_OFF, g_Bl + (size_t)nc*128*JP, 128*JP*2, mb);
        }
    }

    // ---- time logits ----
    {
        int p  = tid >> 2;
        int d0 = (tid & 3)*6;
        const float* arow = s_attn + p*JP;
        const float* stl  = (const float*)(sm + SM_TLB);
        float acc6[6] = {0,0,0,0,0,0};
        #pragma unroll 4
        for (int j = 0; j < J; j++) {
            float a = arow[j];
            const float* tr = stl + j*TS + d0;
            #pragma unroll
            for (int i = 0; i < 6; i++) acc6[i] = fmaf(a, tr[i], acc6[i]);
        }
        float* orow = out_tl + (size_t)(n0 + p)*TS + d0;
        #pragma unroll
        for (int i = 0; i < 6; i++)
            orow[i] = acc6[i] + __ldg(b_time + d0 + i);
    }
}

// ---------------- launch ----------------
extern "C" void kernel_launch(void* const* d_in, const int* in_sizes, int n_in,
                              void* d_out, int out_size)
{
    const float* ts_emb    = (const float*)d_in[0];
    const int*   user_x    = (const int*)  d_in[3];
    const int*   hour_x    = (const int*)  d_in[4];
    const int*   hour_mask = (const int*)  d_in[5];
    const float* upt       = (const float*)d_in[6];
    const float* Wq        = (const float*)d_in[7];
    const float* bq        = (const float*)d_in[8];
    const float* Wk        = (const float*)d_in[9];
    const float* bk        = (const float*)d_in[10];
    const float* Wv        = (const float*)d_in[11];
    const float* bv        = (const float*)d_in[12];
    const float* Wu        = (const float*)d_in[13];
    const float* bu        = (const float*)d_in[14];
    const float* Wt        = (const float*)d_in[15];
    const float* bt        = (const float*)d_in[16];

    float* out_emb = (float*)d_out;
    float* out_tl  = out_emb + (size_t)NPOS * D;

    cudaFuncSetAttribute(k_main, cudaFuncAttributeMaxDynamicSharedMemorySize, SM_TOTAL);

    k_pre1<<<1088, 256>>>(ts_emb, user_x, upt, Wq, bq, Wk, bk, Wv, bv);
    k_pre2<<<804, 256>>>(Wu, Wt);
    k_pre3<<<768, 256>>>();
    k_main<<<256, 512, SM_TOTAL>>>(hour_x, hour_mask, bu, bt, out_emb, out_tl);
}